// round 4
// baseline (speedup 1.0000x reference)
#include <cuda_runtime.h>
#include <cuda_bf16.h>

// ContourIntegrationLayer: depthwise 3x3 conv (center tap zeroed) + residual.
// x: [B=32, H=56, W=56, C=256] fp32 NHWC ; kernel: [3,3,256] fp32.
//
// R4: rotating accumulators + explicit double-buffered row prefetch.
// Uniform loop consumes rows h0-1 .. h0+H_SEG; consuming row r:
//   out[r-1] += bottom(r)  -> store   (gated: i>=2)
//   out[r]   += mid(r) + residual(center)
//   out[r+1]  = top(r)
// Loads for the next row are issued one full iteration before use, giving
// each warp ~6 float4 LDGs in flight (vs 3 in R2). 3 blocks/SM, 84-reg cap.

#define BD 32
#define HD 56
#define WD 56
#define CD 256
#define C4D 64            // CD / 4 float4 lanes
#define H_SEG 14          // 56 / 4 segments
#define W_TILE 4

__device__ __forceinline__ float4 f4z() { return make_float4(0.f, 0.f, 0.f, 0.f); }

__device__ __forceinline__ void fma4(float4& a, const float4& k, const float4& v) {
    a.x = fmaf(k.x, v.x, a.x);
    a.y = fmaf(k.y, v.y, a.y);
    a.z = fmaf(k.z, v.z, a.z);
    a.w = fmaf(k.w, v.w, a.w);
}

__device__ __forceinline__ void add4(float4& a, const float4& v) {
    a.x += v.x; a.y += v.y; a.z += v.z; a.w += v.w;
}

__global__ __launch_bounds__(256, 3)
void contour_integration_kernel(const float* __restrict__ x,
                                const float* __restrict__ ker,
                                float* __restrict__ out) {
    const int c4 = threadIdx.x;                       // 0..63
    const int w  = blockIdx.x * W_TILE + threadIdx.y; // 0..55
    const int h0 = blockIdx.y * H_SEG;
    const int b  = blockIdx.z;

    const bool wl = (w > 0);
    const bool wr = (w < WD - 1);
    const float4 z = f4z();

    // Per-channel taps; boundary columns handled by zeroing taps so the
    // clamped halo loads contribute nothing. Center (1,1) excluded.
    const float4* kp = (const float4*)ker;
    const float4 k00 = wl ? kp[0 * C4D + c4] : z;
    const float4 k01 =      kp[1 * C4D + c4];
    const float4 k02 = wr ? kp[2 * C4D + c4] : z;
    const float4 k10 = wl ? kp[3 * C4D + c4] : z;
    const float4 k12 = wr ? kp[5 * C4D + c4] : z;
    const float4 k20 = wl ? kp[6 * C4D + c4] : z;
    const float4 k21 =      kp[7 * C4D + c4];
    const float4 k22 = wr ? kp[8 * C4D + c4] : z;

    // Clamped halo offsets: boundary threads re-load center (L1 hit).
    const int offL = wl ? -C4D : 0;
    const int offR = wr ?  C4D : 0;

    const float4* xp = (const float4*)x;
    float4*       op = (float4*)out;

    const long rowstride = (long)WD * C4D;
    const long base = ((long)b * HD * WD + (long)w) * C4D + c4;

    // Double buffers: c* = row being consumed, n* = row in flight.
    float4 cl, cc, cr, nl, nc, nr;

    // Prologue: issue loads for rows h0-1 and h0 back-to-back.
    if (h0 > 0) {
        const float4* p = xp + base + (long)(h0 - 1) * rowstride;
        cl = p[offL]; cc = p[0]; cr = p[offR];
    } else {
        cl = z; cc = z; cr = z;
    }
    {
        const float4* p = xp + base + (long)h0 * rowstride;
        nl = p[offL]; nc = p[0]; nr = p[offR];
    }

    float4 A = z;   // partial of out[r-1] entering iteration (needs bottom)
    float4 B = z;   // partial of out[r]   entering iteration (has top)

    // Consume rows r = h0-1+i for i = 0 .. H_SEG+1.
    #pragma unroll
    for (int i = 0; i <= H_SEG + 1; ++i) {
        const long r = (long)h0 - 1 + i;

        // Complete and store out[r-1] (in-segment iff i >= 2).
        if (i >= 2) {
            float4 o = A;
            fma4(o, k20, cl); fma4(o, k21, cc); fma4(o, k22, cr);
            __stcs(op + base + (r - 1) * rowstride, o);
        }

        // Advance partials with row r's mid/residual and top taps.
        float4 An = B;
        add4(An, cc);                               // residual
        fma4(An, k10, cl); fma4(An, k12, cr);
        float4 Bn = z;
        fma4(Bn, k00, cl); fma4(Bn, k01, cc); fma4(Bn, k02, cr);
        A = An; B = Bn;

        // Rotate prefetched row into current; prefetch row r+2.
        cl = nl; cc = nc; cr = nr;
        if (i <= H_SEG - 1) {                       // row r+2 still consumed?
            const long rn = r + 2;
            if (rn < HD) {
                const float4* p = xp + base + rn * rowstride;
                nl = p[offL]; nc = p[0]; nr = p[offR];
            } else {
                nl = z; nc = z; nr = z;
            }
        }
    }
}

extern "C" void kernel_launch(void* const* d_in, const int* in_sizes, int n_in,
                              void* d_out, int out_size) {
    const float* x   = (const float*)d_in[0];   // [32,56,56,256]
    const float* ker = (const float*)d_in[1];   // [3,3,256]
    float*       out = (float*)d_out;

    dim3 block(C4D, W_TILE);                    // 64 x 4 = 256 threads
    dim3 grid(WD / W_TILE, HD / H_SEG, BD);     // 14 x 4 x 32 = 1792 blocks
    contour_integration_kernel<<<grid, block>>>(x, ker, out);
}